// round 7
// baseline (speedup 1.0000x reference)
#include <cuda_runtime.h>
#include <cuda_bf16.h>
#include <cstdint>

#define NPTS 8192
#define DIMX 256
#define DIMZ 64
#define KNN  5
#define EPSF 1e-7f

#define NTILE 128                          // 8192 / 64 row-tiles
#define NPAIRS (NTILE * (NTILE + 1) / 2)   // 8256
#define PTOP 4
#define GTOP 8
#define U64MAX 0xFFFFFFFFFFFFFFFFull

// ---- scratch ----
__device__ float g_sq[NPTS];
__device__ __nv_bfloat16 g_xbf[NPTS * DIMX];
__device__ unsigned long long g_p[(size_t)NPTS * NTILE * PTOP];   // 33.5 MB
__device__ int   g_cand[NPTS][GTOP];
__device__ float g_bsum[1024];

__device__ __forceinline__ uint32_t smem_u32(const void* p) {
    uint32_t a;
    asm("{ .reg .u64 t; cvta.to.shared.u64 t, %1; cvt.u32.u64 %0, t; }" : "=r"(a) : "l"(p));
    return a;
}

#define LDSM_X4(r0, r1, r2, r3, addr) \
    asm volatile("ldmatrix.sync.aligned.m8n8.x4.shared.b16 {%0,%1,%2,%3}, [%4];" \
                 : "=r"(r0), "=r"(r1), "=r"(r2), "=r"(r3) : "r"(addr))

#define MMA16816(c, a0, a1, a2, a3, b0, b1) \
    asm volatile("mma.sync.aligned.m16n8k16.row.col.f32.bf16.bf16.f32 " \
                 "{%0,%1,%2,%3}, {%4,%5,%6,%7}, {%8,%9}, {%0,%1,%2,%3};" \
                 : "+f"((c)[0]), "+f"((c)[1]), "+f"((c)[2]), "+f"((c)[3]) \
                 : "r"(a0), "r"(a1), "r"(a2), "r"(a3), "r"(b0), "r"(b1))

#define CP_ASYNC16(dst, src) \
    asm volatile("cp.async.cg.shared.global [%0], [%1], 16;" :: "r"(dst), "l"(src))
#define CP_COMMIT() asm volatile("cp.async.commit_group;")
#define CP_WAIT0()  asm volatile("cp.async.wait_group 0;")

// monotone float->u32; key = (enc<<32)|idx : u64 '<' == lexicographic (val,idx)
__device__ __forceinline__ unsigned long long packkey(float v, int idx) {
    uint32_t u = __float_as_uint(v);
    u = (u >> 31) ? ~u : (u | 0x80000000u);
    return ((unsigned long long)u << 32) | (uint32_t)idx;
}
template<int NL>
__device__ __forceinline__ void insertU(unsigned long long l[NL], unsigned long long v) {
    if (v < l[NL - 1]) {
        l[NL - 1] = v;
#pragma unroll
        for (int s = NL - 1; s > 0; --s)
            if (l[s] < l[s - 1]) { unsigned long long t = l[s]; l[s] = l[s - 1]; l[s - 1] = t; }
    }
}
__device__ __forceinline__ bool lessp(float v, int i, float v2, int i2) {
    return (v < v2) || (v == v2 && i < i2);
}
__device__ __forceinline__ void insert5(float lv[KNN], int li[KNN], float v, int idx) {
    if (lessp(v, idx, lv[KNN - 1], li[KNN - 1])) {
        lv[KNN - 1] = v; li[KNN - 1] = idx;
#pragma unroll
        for (int s = KNN - 1; s > 0; --s) {
            if (lessp(lv[s], li[s], lv[s - 1], li[s - 1])) {
                float tv = lv[s]; lv[s] = lv[s - 1]; lv[s - 1] = tv;
                int   ti = li[s]; li[s] = li[s - 1]; li[s - 1] = ti;
            }
        }
    }
}

// ================= fused fp32->bf16 + squared row norms =================
__global__ void cvtsq_kernel(const float* __restrict__ X) {
    int warp = (blockIdx.x * blockDim.x + threadIdx.x) >> 5;
    int lane = threadIdx.x & 31;
    if (warp >= NPTS) return;
    const float2* src = (const float2*)(X + (size_t)warp * DIMX);
    __nv_bfloat162* dst = (__nv_bfloat162*)(g_xbf + (size_t)warp * DIMX);
    float s = 0.f;
#pragma unroll
    for (int t = 0; t < 4; ++t) {
        float2 v = src[lane + 32 * t];
        s = fmaf(v.x, v.x, fmaf(v.y, v.y, s));
        dst[lane + 32 * t] = __floats2bfloat162_rn(v.x, v.y);
    }
#pragma unroll
    for (int o = 16; o > 0; o >>= 1) s += __shfl_xor_sync(0xffffffffu, s, o);
    if (lane == 0) g_sq[warp] = s;
}

// ====== symmetric tile-pair screen: cp.async double-buffered, packed top-4 ======
__global__ __launch_bounds__(256) void screen_pair_kernel() {
    __shared__ __align__(16) uint8_t smRaw[32768];   // 2 stages x (A 8K + B 8K); smC overlays
    __shared__ float sqI[64], sqJ[64];
    float* smC = (float*)smRaw;                      // 64*65*4 = 16640 B, live post-mainloop

    const int tid = threadIdx.x;
    const int wid = tid >> 5;
    const int lane = tid & 31;
    const uint32_t sb = smem_u32(smRaw);

    // ---- linear pair index -> (ti, tj), ti <= tj ----
    const int k = blockIdx.x;
    int i = (int)(128.5f - sqrtf(128.5f * 128.5f - 2.0f * (float)k));
    if (i < 0) i = 0; if (i > NTILE - 1) i = NTILE - 1;
    while (i > 0 && (i * NTILE - i * (i - 1) / 2) > k) --i;
    while (((i + 1) * NTILE - (i + 1) * i / 2) <= k) ++i;
    const int ti = i;
    const int tj = i + (k - (i * NTILE - i * (i - 1) / 2));
    const int rbI = ti * 64, rbJ = tj * 64;

    if (tid < 64) { sqI[tid] = g_sq[rbI + tid]; sqJ[tid] = g_sq[rbJ + tid]; }

    // staging map: thread covers rows rr, rr+32; 16B-chunk cc
    const int rr = tid >> 3, cc = tid & 7;
    const uint32_t dstOffA0 = (uint32_t)rr * 128 + (((uint32_t)cc ^ (rr & 7)) << 4);
    const uint32_t dstOffA1 = (uint32_t)(rr + 32) * 128 + (((uint32_t)cc ^ ((rr + 32) & 7)) << 4);

    // issue one k-chunk's cp.asyncs into stage p
    auto issue_chunk = [&](int kc, int p) {
        uint32_t base = sb + (uint32_t)p * 16384;
        const __nv_bfloat16* sA = g_xbf + (size_t)(rbI + rr) * DIMX + kc * 64 + cc * 8;
        const __nv_bfloat16* sB = g_xbf + (size_t)(rbJ + rr) * DIMX + kc * 64 + cc * 8;
        CP_ASYNC16(base + dstOffA0,        sA);
        CP_ASYNC16(base + dstOffA1,        sA + 32 * DIMX);
        CP_ASYNC16(base + 8192 + dstOffA0, sB);
        CP_ASYNC16(base + 8192 + dstOffA1, sB + 32 * DIMX);
    };

    float c[4][4];
#pragma unroll
    for (int j = 0; j < 4; ++j)
#pragma unroll
        for (int q = 0; q < 4; ++q) c[j][q] = 0.f;

    // fragment addressing (warp (wid&3)=row group, (wid>>2)=col half)
    const int rA = (wid & 3) * 16 + (lane & 15);
    const uint32_t aOff = (uint32_t)rA * 128;
    const uint32_t aSw = (uint32_t)(rA & 7);
    const uint32_t aHi = (uint32_t)(lane >> 4);
    const int bLane = (lane & 7) + ((lane >> 4) << 3);
    const uint32_t bOff = 8192 + (uint32_t)bLane * 128;
    const uint32_t bSw = (uint32_t)(lane & 7);
    const uint32_t bHi = (uint32_t)((lane >> 3) & 1);
    const uint32_t bBlk = (uint32_t)(wid >> 2) * 2;

    issue_chunk(0, 0);
    CP_COMMIT();

    for (int kc = 0; kc < 4; ++kc) {
        CP_WAIT0();
        __syncthreads();            // chunk kc visible; prior-iteration reads of stage (kc+1)&1 done
        if (kc + 1 < 4) { issue_chunk(kc + 1, (kc + 1) & 1); CP_COMMIT(); }

        const uint32_t stage = sb + (uint32_t)(kc & 1) * 16384;
#pragma unroll
        for (int ks = 0; ks < 4; ++ks) {
            uint32_t a0, a1, a2, a3;
            LDSM_X4(a0, a1, a2, a3, stage + aOff + ((((uint32_t)ks * 2 + aHi) ^ aSw) << 4));
            uint32_t ccB = (((uint32_t)ks * 2 + bHi) ^ bSw) << 4;
#pragma unroll
            for (int p = 0; p < 2; ++p) {
                uint32_t b0, b1, b2, b3;
                LDSM_X4(b0, b1, b2, b3, stage + bOff + (bBlk + p) * 2048 + ccB);
                MMA16816(c[2 * p],     a0, a1, a2, a3, b0, b1);
                MMA16816(c[2 * p + 1], a0, a1, a2, a3, b2, b3);
            }
        }
    }
    __syncthreads();   // all LDSM reads done before smC overlays the buffers

    // ---- stage C (stride 65) ----
    {
        const int r0 = (wid & 3) * 16 + (lane >> 2), r1 = r0 + 8;
        const int cq = (wid >> 2) * 32 + 2 * (lane & 3);
#pragma unroll
        for (int j = 0; j < 4; ++j) {
            int col = cq + j * 8;
            smC[r0 * 65 + col]     = c[j][0];
            smC[r0 * 65 + col + 1] = c[j][1];
            smC[r1 * 65 + col]     = c[j][2];
            smC[r1 * 65 + col + 1] = c[j][3];
        }
    }
    __syncthreads();

    // ---- row side: 4 scanners per row, 16 cols each ----
    {
        const int r = tid >> 2, h = tid & 3;
        const int grow = rbI + r;
        unsigned long long l[PTOP];
#pragma unroll
        for (int s = 0; s < PTOP; ++s) l[s] = U64MAX;
#pragma unroll
        for (int s = 0; s < 16; ++s) {
            int cl = h * 16 + s;
            int idx = rbJ + cl;
            if (idx != grow)
                insertU<PTOP>(l, packkey(fmaf(-2.f, smC[r * 65 + cl], sqJ[cl]), idx));
        }
#pragma unroll
        for (int d = 1; d < 4; d <<= 1) {
            unsigned long long rv[PTOP];
#pragma unroll
            for (int s = 0; s < PTOP; ++s) rv[s] = __shfl_xor_sync(0xffffffffu, l[s], d);
            for (int s = 0; s < PTOP; ++s) {          // remote sorted: early break
                if (rv[s] >= l[PTOP - 1]) break;
                insertU<PTOP>(l, rv[s]);
            }
        }
        if (h == 0) {
            unsigned long long* dst = &g_p[((size_t)grow * NTILE + tj) * PTOP];
            ((ulonglong2*)dst)[0] = make_ulonglong2(l[0], l[1]);
            ((ulonglong2*)dst)[1] = make_ulonglong2(l[2], l[3]);
        }
    }

    // ---- col side (skip diagonal pair) ----
    if (ti != tj) {
        const int c2 = tid >> 2, h = tid & 3;
        const int grow = rbJ + c2;
        unsigned long long l[PTOP];
#pragma unroll
        for (int s = 0; s < PTOP; ++s) l[s] = U64MAX;
#pragma unroll
        for (int s = 0; s < 16; ++s) {
            int rl = h * 16 + s;
            insertU<PTOP>(l, packkey(fmaf(-2.f, smC[rl * 65 + c2], sqI[rl]), rbI + rl));
        }
#pragma unroll
        for (int d = 1; d < 4; d <<= 1) {
            unsigned long long rv[PTOP];
#pragma unroll
            for (int s = 0; s < PTOP; ++s) rv[s] = __shfl_xor_sync(0xffffffffu, l[s], d);
            for (int s = 0; s < PTOP; ++s) {
                if (rv[s] >= l[PTOP - 1]) break;
                insertU<PTOP>(l, rv[s]);
            }
        }
        if (h == 0) {
            unsigned long long* dst = &g_p[((size_t)grow * NTILE + ti) * PTOP];
            ((ulonglong2*)dst)[0] = make_ulonglong2(l[0], l[1]);
            ((ulonglong2*)dst)[1] = make_ulonglong2(l[2], l[3]);
        }
    }
}

// ======= merge: 1 row per 128-thr block, 1 tile per lane, early-break rounds =======
__global__ __launch_bounds__(128) void merge_kernel() {
    __shared__ unsigned long long sh[4][GTOP];
    const int row = blockIdx.x;
    const int tid = threadIdx.x, wid = tid >> 5, lane = tid & 31;

    const unsigned long long* src = &g_p[((size_t)row * NTILE + tid) * PTOP];
    ulonglong2 v0 = ((const ulonglong2*)src)[0];
    ulonglong2 v1 = ((const ulonglong2*)src)[1];
    unsigned long long l[GTOP] = { v0.x, v0.y, v1.x, v1.y, U64MAX, U64MAX, U64MAX, U64MAX };

#pragma unroll
    for (int d = 1; d < 32; d <<= 1) {
        unsigned long long rv[GTOP];
#pragma unroll
        for (int s = 0; s < GTOP; ++s) rv[s] = __shfl_xor_sync(0xffffffffu, l[s], d);
        for (int s = 0; s < GTOP; ++s) {     // remote sorted ascending: early break
            if (rv[s] >= l[GTOP - 1]) break;
            insertU<GTOP>(l, rv[s]);
        }
    }
    if (lane == 0) {
#pragma unroll
        for (int s = 0; s < GTOP; ++s) sh[wid][s] = l[s];
    }
    __syncthreads();
    if (wid == 0) {
        for (int w = 1; w < 4; ++w)
            for (int s = 0; s < GTOP; ++s) {
                unsigned long long rv = sh[w][s];
                if (rv >= l[GTOP - 1]) break;
                insertU<GTOP>(l, rv);
            }
        if (lane == 0) {
#pragma unroll
            for (int s = 0; s < GTOP; ++s) g_cand[row][s] = (int)(uint32_t)(l[s] & 0xffffffffu);
        }
    }
}

// ===== fused: exact fp32 re-rank -> lid_X -> z-distances -> lid_Z -> block sum =====
__global__ __launch_bounds__(256) void rerank_z_kernel(const float* __restrict__ X,
                                                       const float* __restrict__ Z) {
    __shared__ float bsum[8];
    const int warp = (blockIdx.x * blockDim.x + threadIdx.x) >> 5;
    const int lane = threadIdx.x & 31;
    const int wid = threadIdx.x >> 5;
    const int row = warp;

    float xi[8];
#pragma unroll
    for (int t = 0; t < 8; ++t) xi[t] = X[(size_t)row * DIMX + lane + 32 * t];
    const float sqr = g_sq[row];

    float lv[KNN]; int li[KNN];
#pragma unroll
    for (int s = 0; s < KNN; ++s) { lv[s] = 3.4e38f; li[s] = 0x7fffffff; }

#pragma unroll
    for (int s = 0; s < GTOP; ++s) {
        int j = g_cand[row][s];
        const float* xr = X + (size_t)j * DIMX;
        float d = 0.f;
#pragma unroll
        for (int t = 0; t < 8; ++t) d = fmaf(xi[t], xr[lane + 32 * t], d);
#pragma unroll
        for (int o = 16; o > 0; o >>= 1) d += __shfl_xor_sync(0xffffffffu, d, o);
        insert5(lv, li, sqr + g_sq[j] - 2.f * d, j);   // identical on all lanes
    }

    float lidX;
    {
        float vK = sqrtf(fmaxf(lv[KNN - 1], 0.f)) + EPSF;
        float lgK = log10f(vK);
        lidX = 0.f;
#pragma unroll
        for (int s = 0; s < KNN; ++s)
            lidX += lgK - log10f(sqrtf(fmaxf(lv[s], 0.f)) + EPSF);
    }

    // z side in the same warp (li replicated across lanes)
    float z0 = Z[(size_t)row * DIMZ + lane];
    float z1 = Z[(size_t)row * DIMZ + 32 + lane];
    float e[KNN];
#pragma unroll
    for (int s = 0; s < KNN; ++s) {
        int m = li[s];
        float d0 = z0 - Z[(size_t)m * DIMZ + lane];
        float d1 = z1 - Z[(size_t)m * DIMZ + 32 + lane];
        float ss = fmaf(d0, d0, d1 * d1);
#pragma unroll
        for (int o = 16; o > 0; o >>= 1) ss += __shfl_xor_sync(0xffffffffu, ss, o);
        e[s] = sqrtf(ss) + EPSF;
    }
    float lgK = log10f(e[KNN - 1]);
    float lidZ = 0.f;
#pragma unroll
    for (int s = 0; s < KNN; ++s) lidZ += lgK - log10f(e[s]);
    float d = lidX - lidZ;

    if (lane == 0) bsum[wid] = d * d;
    __syncthreads();
    if (threadIdx.x == 0) {
        float s = 0.f;
#pragma unroll
        for (int w = 0; w < 8; ++w) s += bsum[w];
        g_bsum[blockIdx.x] = s;
    }
}

// ================= final deterministic reduction over 1024 block sums =================
__global__ void final_reduce(float* __restrict__ out) {
    __shared__ float sh[256];
    int t = threadIdx.x;
    float s = g_bsum[t] + g_bsum[t + 256] + g_bsum[t + 512] + g_bsum[t + 768];
    sh[t] = s;
    __syncthreads();
    for (int o = 128; o > 0; o >>= 1) {
        if (t < o) sh[t] += sh[t + o];
        __syncthreads();
    }
    if (t == 0) out[0] = sh[0] * (1.f / ((float)NPTS * KNN * 10.f));
}

extern "C" void kernel_launch(void* const* d_in, const int* in_sizes, int n_in,
                              void* d_out, int out_size) {
    const float* X = (const float*)d_in[0];   // (8192, 256)
    const float* Z = (const float*)d_in[1];   // (8192, 64)
    float* out = (float*)d_out;

    cvtsq_kernel<<<NPTS / 8, 256>>>(X);
    screen_pair_kernel<<<NPAIRS, 256>>>();
    merge_kernel<<<NPTS, 128>>>();
    rerank_z_kernel<<<NPTS / 8, 256>>>(X, Z);
    final_reduce<<<1, 256>>>(out);
}

// round 8
// speedup vs baseline: 1.8542x; 1.8542x over previous
#include <cuda_runtime.h>
#include <cuda_bf16.h>
#include <cstdint>

#define NPTS 8192
#define DIMX 256
#define DIMZ 64
#define KNN  5
#define EPSF 1e-7f

#define NTILE 128                          // 8192 / 64 row-tiles
#define NPAIRS (NTILE * (NTILE + 1) / 2)   // 8256
#define PTOP 4
#define GTOP 8
#define U64MAX 0xFFFFFFFFFFFFFFFFull

// ---- scratch ----
__device__ float g_sq[NPTS];
__device__ __nv_bfloat16 g_xbf[NPTS * DIMX];
__device__ unsigned long long g_p[(size_t)NPTS * NTILE * PTOP];   // 33.5 MB
__device__ int   g_cand[NPTS][GTOP];
__device__ float g_bsum[1024];

__device__ __forceinline__ uint32_t smem_u32(const void* p) {
    uint32_t a;
    asm("{ .reg .u64 t; cvta.to.shared.u64 t, %1; cvt.u32.u64 %0, t; }" : "=r"(a) : "l"(p));
    return a;
}

#define LDSM_X4(r0, r1, r2, r3, addr) \
    asm volatile("ldmatrix.sync.aligned.m8n8.x4.shared.b16 {%0,%1,%2,%3}, [%4];" \
                 : "=r"(r0), "=r"(r1), "=r"(r2), "=r"(r3) : "r"(addr))

#define MMA16816(c, a0, a1, a2, a3, b0, b1) \
    asm volatile("mma.sync.aligned.m16n8k16.row.col.f32.bf16.bf16.f32 " \
                 "{%0,%1,%2,%3}, {%4,%5,%6,%7}, {%8,%9}, {%0,%1,%2,%3};" \
                 : "+f"((c)[0]), "+f"((c)[1]), "+f"((c)[2]), "+f"((c)[3]) \
                 : "r"(a0), "r"(a1), "r"(a2), "r"(a3), "r"(b0), "r"(b1))

// monotone float->u32; key = (enc<<32)|idx : u64 '<' == lexicographic (val,idx)
__device__ __forceinline__ unsigned long long packkey(float v, int idx) {
    uint32_t u = __float_as_uint(v);
    u = (u >> 31) ? ~u : (u | 0x80000000u);
    return ((unsigned long long)u << 32) | (uint32_t)idx;
}
template<int NL>
__device__ __forceinline__ void insertU(unsigned long long l[NL], unsigned long long v) {
    if (v < l[NL - 1]) {
        l[NL - 1] = v;
#pragma unroll
        for (int s = NL - 1; s > 0; --s)
            if (l[s] < l[s - 1]) { unsigned long long t = l[s]; l[s] = l[s - 1]; l[s - 1] = t; }
    }
}
__device__ __forceinline__ bool lessp(float v, int i, float v2, int i2) {
    return (v < v2) || (v == v2 && i < i2);
}
__device__ __forceinline__ void insert5(float lv[KNN], int li[KNN], float v, int idx) {
    if (lessp(v, idx, lv[KNN - 1], li[KNN - 1])) {
        lv[KNN - 1] = v; li[KNN - 1] = idx;
#pragma unroll
        for (int s = KNN - 1; s > 0; --s) {
            if (lessp(lv[s], li[s], lv[s - 1], li[s - 1])) {
                float tv = lv[s]; lv[s] = lv[s - 1]; lv[s - 1] = tv;
                int   ti = li[s]; li[s] = li[s - 1]; li[s - 1] = ti;
            }
        }
    }
}

// ================= fused fp32->bf16 + squared row norms =================
__global__ void cvtsq_kernel(const float* __restrict__ X) {
    int warp = (blockIdx.x * blockDim.x + threadIdx.x) >> 5;
    int lane = threadIdx.x & 31;
    if (warp >= NPTS) return;
    const float2* src = (const float2*)(X + (size_t)warp * DIMX);
    __nv_bfloat162* dst = (__nv_bfloat162*)(g_xbf + (size_t)warp * DIMX);
    float s = 0.f;
#pragma unroll
    for (int t = 0; t < 4; ++t) {
        float2 v = src[lane + 32 * t];
        s = fmaf(v.x, v.x, fmaf(v.y, v.y, s));
        dst[lane + 32 * t] = __floats2bfloat162_rn(v.x, v.y);
    }
#pragma unroll
    for (int o = 16; o > 0; o >>= 1) s += __shfl_xor_sync(0xffffffffu, s, o);
    if (lane == 0) g_sq[warp] = s;
}

// ====== symmetric tile-pair screen (R6-proven register-staged mainloop) ======
__global__ __launch_bounds__(256) void screen_pair_kernel() {
    __shared__ __align__(16) uint8_t smA[64 * 128];   // 64 rows x 64 bf16 k-chunk
    __shared__ __align__(16) uint8_t smB[64 * 128];
    __shared__ float smC[64 * 65];
    __shared__ float sqI[64], sqJ[64];

    const int tid = threadIdx.x;
    const int wid = tid >> 5;
    const int lane = tid & 31;

    // ---- linear pair index -> (ti, tj), ti <= tj ----
    const int k = blockIdx.x;
    int i = (int)(128.5f - sqrtf(128.5f * 128.5f - 2.0f * (float)k));
    if (i < 0) i = 0; if (i > NTILE - 1) i = NTILE - 1;
    while (i > 0 && (i * NTILE - i * (i - 1) / 2) > k) --i;
    while (((i + 1) * NTILE - (i + 1) * i / 2) <= k) ++i;
    const int ti = i;
    const int tj = i + (k - (i * NTILE - i * (i - 1) / 2));
    const int rbI = ti * 64, rbJ = tj * 64;

    if (tid < 64) { sqI[tid] = g_sq[rbI + tid]; sqJ[tid] = g_sq[rbJ + tid]; }

    // staging map: 512 16B-chunks per tile-chunk; thread handles chunk tid and tid+256
    const int rr = tid >> 3, cc = tid & 7;   // r in 0..31, +32 for second

    uint4 pa[2], pb[2];
#pragma unroll
    for (int it = 0; it < 2; ++it) {
        pa[it] = *(const uint4*)(g_xbf + (size_t)(rbI + rr + it * 32) * DIMX + cc * 8);
        pb[it] = *(const uint4*)(g_xbf + (size_t)(rbJ + rr + it * 32) * DIMX + cc * 8);
    }

    float c[4][4];
#pragma unroll
    for (int j = 0; j < 4; ++j)
#pragma unroll
        for (int q = 0; q < 4; ++q) c[j][q] = 0.f;

    // fragment addressing: warp (wid&3) -> row group, (wid>>2) -> col half
    const int rA = (wid & 3) * 16 + (lane & 15);
    const uint32_t aRowB = smem_u32(smA) + (uint32_t)rA * 128;
    const uint32_t aSw = (uint32_t)(rA & 7);
    const uint32_t aHi = (uint32_t)(lane >> 4);
    const int bLane = (lane & 7) + ((lane >> 4) << 3);
    const uint32_t bRowB = smem_u32(smB) + (uint32_t)bLane * 128;
    const uint32_t bSw = (uint32_t)(lane & 7);
    const uint32_t bHi = (uint32_t)((lane >> 3) & 1);
    const uint32_t bBlk = (uint32_t)(wid >> 2) * 2;   // 16-col block base

    for (int kc = 0; kc < 4; ++kc) {
        __syncthreads();
#pragma unroll
        for (int it = 0; it < 2; ++it) {
            int r = rr + it * 32;
            *(uint4*)(smA + r * 128 + (((uint32_t)cc ^ (r & 7)) << 4)) = pa[it];
            *(uint4*)(smB + r * 128 + (((uint32_t)cc ^ (r & 7)) << 4)) = pb[it];
        }
        __syncthreads();
        if (kc < 3) {
#pragma unroll
            for (int it = 0; it < 2; ++it) {
                pa[it] = *(const uint4*)(g_xbf + (size_t)(rbI + rr + it * 32) * DIMX + (kc + 1) * 64 + cc * 8);
                pb[it] = *(const uint4*)(g_xbf + (size_t)(rbJ + rr + it * 32) * DIMX + (kc + 1) * 64 + cc * 8);
            }
        }
#pragma unroll
        for (int ks = 0; ks < 4; ++ks) {
            uint32_t a0, a1, a2, a3;
            LDSM_X4(a0, a1, a2, a3, aRowB + ((((uint32_t)ks * 2 + aHi) ^ aSw) << 4));
            uint32_t ccB = (((uint32_t)ks * 2 + bHi) ^ bSw) << 4;
#pragma unroll
            for (int p = 0; p < 2; ++p) {
                uint32_t b0, b1, b2, b3;
                LDSM_X4(b0, b1, b2, b3, bRowB + (bBlk + p) * 2048 + ccB);
                MMA16816(c[2 * p],     a0, a1, a2, a3, b0, b1);
                MMA16816(c[2 * p + 1], a0, a1, a2, a3, b2, b3);
            }
        }
    }

    // ---- stage C to smem (stride 65) ----
    {
        const int r0 = (wid & 3) * 16 + (lane >> 2), r1 = r0 + 8;
        const int cq = (wid >> 2) * 32 + 2 * (lane & 3);
#pragma unroll
        for (int j = 0; j < 4; ++j) {
            int col = cq + j * 8;
            smC[r0 * 65 + col]     = c[j][0];
            smC[r0 * 65 + col + 1] = c[j][1];
            smC[r1 * 65 + col]     = c[j][2];
            smC[r1 * 65 + col + 1] = c[j][3];
        }
    }
    __syncthreads();

    // ---- row side: 4 scanners per row, 16 cols each ----
    {
        const int r = tid >> 2, h = tid & 3;
        const int grow = rbI + r;
        unsigned long long l[PTOP];
#pragma unroll
        for (int s = 0; s < PTOP; ++s) l[s] = U64MAX;
#pragma unroll
        for (int s = 0; s < 16; ++s) {
            int cl = h * 16 + s;
            int idx = rbJ + cl;
            if (idx != grow)
                insertU<PTOP>(l, packkey(fmaf(-2.f, smC[r * 65 + cl], sqJ[cl]), idx));
        }
#pragma unroll
        for (int d = 1; d < 4; d <<= 1) {
            unsigned long long rv[PTOP];
#pragma unroll
            for (int s = 0; s < PTOP; ++s) rv[s] = __shfl_xor_sync(0xffffffffu, l[s], d);
            for (int s = 0; s < PTOP; ++s) {          // remote sorted: early break
                if (rv[s] >= l[PTOP - 1]) break;
                insertU<PTOP>(l, rv[s]);
            }
        }
        if (h == 0) {
            unsigned long long* dst = &g_p[((size_t)grow * NTILE + tj) * PTOP];
            ((ulonglong2*)dst)[0] = make_ulonglong2(l[0], l[1]);
            ((ulonglong2*)dst)[1] = make_ulonglong2(l[2], l[3]);
        }
    }

    // ---- col side (skip diagonal pair) ----
    if (ti != tj) {
        const int c2 = tid >> 2, h = tid & 3;
        const int grow = rbJ + c2;
        unsigned long long l[PTOP];
#pragma unroll
        for (int s = 0; s < PTOP; ++s) l[s] = U64MAX;
#pragma unroll
        for (int s = 0; s < 16; ++s) {
            int rl = h * 16 + s;
            insertU<PTOP>(l, packkey(fmaf(-2.f, smC[rl * 65 + c2], sqI[rl]), rbI + rl));
        }
#pragma unroll
        for (int d = 1; d < 4; d <<= 1) {
            unsigned long long rv[PTOP];
#pragma unroll
            for (int s = 0; s < PTOP; ++s) rv[s] = __shfl_xor_sync(0xffffffffu, l[s], d);
            for (int s = 0; s < PTOP; ++s) {
                if (rv[s] >= l[PTOP - 1]) break;
                insertU<PTOP>(l, rv[s]);
            }
        }
        if (h == 0) {
            unsigned long long* dst = &g_p[((size_t)grow * NTILE + ti) * PTOP];
            ((ulonglong2*)dst)[0] = make_ulonglong2(l[0], l[1]);
            ((ulonglong2*)dst)[1] = make_ulonglong2(l[2], l[3]);
        }
    }
}

// ======= merge (R6 shape: warp per row) + early-break on sorted streams =======
__global__ void merge_kernel() {
    int warp = (blockIdx.x * blockDim.x + threadIdx.x) >> 5;
    int lane = threadIdx.x & 31;
    if (warp >= NPTS) return;
    unsigned long long l[GTOP];
#pragma unroll
    for (int s = 0; s < GTOP; ++s) l[s] = U64MAX;
#pragma unroll
    for (int q = 0; q < 4; ++q) {
        const unsigned long long* src = &g_p[((size_t)warp * NTILE + lane + q * 32) * PTOP];
        ulonglong2 v0 = ((const ulonglong2*)src)[0];
        ulonglong2 v1 = ((const ulonglong2*)src)[1];
        // v0.x < v0.y < v1.x < v1.y (written sorted): early break
        if (v0.x >= l[GTOP - 1]) continue;
        insertU<GTOP>(l, v0.x);
        if (v0.y >= l[GTOP - 1]) continue;
        insertU<GTOP>(l, v0.y);
        if (v1.x >= l[GTOP - 1]) continue;
        insertU<GTOP>(l, v1.x);
        if (v1.y < l[GTOP - 1]) insertU<GTOP>(l, v1.y);
    }
#pragma unroll
    for (int d = 1; d < 32; d <<= 1) {
        unsigned long long rv[GTOP];
#pragma unroll
        for (int s = 0; s < GTOP; ++s) rv[s] = __shfl_xor_sync(0xffffffffu, l[s], d);
        for (int s = 0; s < GTOP; ++s) {     // remote sorted ascending: early break
            if (rv[s] >= l[GTOP - 1]) break;
            insertU<GTOP>(l, rv[s]);
        }
    }
    if (lane == 0) {
#pragma unroll
        for (int s = 0; s < GTOP; ++s) g_cand[warp][s] = (int)(uint32_t)(l[s] & 0xffffffffu);
    }
}

// ===== fused: exact fp32 re-rank -> lid_X -> z-distances -> lid_Z -> block sum =====
__global__ __launch_bounds__(256) void rerank_z_kernel(const float* __restrict__ X,
                                                       const float* __restrict__ Z) {
    __shared__ float bsum[8];
    const int warp = (blockIdx.x * blockDim.x + threadIdx.x) >> 5;
    const int lane = threadIdx.x & 31;
    const int wid = threadIdx.x >> 5;
    const int row = warp;

    float xi[8];
#pragma unroll
    for (int t = 0; t < 8; ++t) xi[t] = X[(size_t)row * DIMX + lane + 32 * t];
    const float sqr = g_sq[row];

    float lv[KNN]; int li[KNN];
#pragma unroll
    for (int s = 0; s < KNN; ++s) { lv[s] = 3.4e38f; li[s] = 0x7fffffff; }

#pragma unroll
    for (int s = 0; s < GTOP; ++s) {
        int j = g_cand[row][s];
        const float* xr = X + (size_t)j * DIMX;
        float d = 0.f;
#pragma unroll
        for (int t = 0; t < 8; ++t) d = fmaf(xi[t], xr[lane + 32 * t], d);
#pragma unroll
        for (int o = 16; o > 0; o >>= 1) d += __shfl_xor_sync(0xffffffffu, d, o);
        insert5(lv, li, sqr + g_sq[j] - 2.f * d, j);   // identical on all lanes
    }

    float lidX;
    {
        float vK = sqrtf(fmaxf(lv[KNN - 1], 0.f)) + EPSF;
        float lgK = log10f(vK);
        lidX = 0.f;
#pragma unroll
        for (int s = 0; s < KNN; ++s)
            lidX += lgK - log10f(sqrtf(fmaxf(lv[s], 0.f)) + EPSF);
    }

    // z side in the same warp (li replicated across lanes)
    float z0 = Z[(size_t)row * DIMZ + lane];
    float z1 = Z[(size_t)row * DIMZ + 32 + lane];
    float e[KNN];
#pragma unroll
    for (int s = 0; s < KNN; ++s) {
        int m = li[s];
        float d0 = z0 - Z[(size_t)m * DIMZ + lane];
        float d1 = z1 - Z[(size_t)m * DIMZ + 32 + lane];
        float ss = fmaf(d0, d0, d1 * d1);
#pragma unroll
        for (int o = 16; o > 0; o >>= 1) ss += __shfl_xor_sync(0xffffffffu, ss, o);
        e[s] = sqrtf(ss) + EPSF;
    }
    float lgK = log10f(e[KNN - 1]);
    float lidZ = 0.f;
#pragma unroll
    for (int s = 0; s < KNN; ++s) lidZ += lgK - log10f(e[s]);
    float d = lidX - lidZ;

    if (lane == 0) bsum[wid] = d * d;
    __syncthreads();
    if (threadIdx.x == 0) {
        float s = 0.f;
#pragma unroll
        for (int w = 0; w < 8; ++w) s += bsum[w];
        g_bsum[blockIdx.x] = s;
    }
}

// ================= final deterministic reduction over 1024 block sums =================
__global__ void final_reduce(float* __restrict__ out) {
    __shared__ float sh[256];
    int t = threadIdx.x;
    float s = g_bsum[t] + g_bsum[t + 256] + g_bsum[t + 512] + g_bsum[t + 768];
    sh[t] = s;
    __syncthreads();
    for (int o = 128; o > 0; o >>= 1) {
        if (t < o) sh[t] += sh[t + o];
        __syncthreads();
    }
    if (t == 0) out[0] = sh[0] * (1.f / ((float)NPTS * KNN * 10.f));
}

extern "C" void kernel_launch(void* const* d_in, const int* in_sizes, int n_in,
                              void* d_out, int out_size) {
    const float* X = (const float*)d_in[0];   // (8192, 256)
    const float* Z = (const float*)d_in[1];   // (8192, 64)
    float* out = (float*)d_out;

    cvtsq_kernel<<<NPTS / 8, 256>>>(X);
    screen_pair_kernel<<<NPAIRS, 256>>>();
    merge_kernel<<<NPTS / 8, 256>>>();
    rerank_z_kernel<<<NPTS / 8, 256>>>(X, Z);
    final_reduce<<<1, 256>>>(out);
}